// round 11
// baseline (speedup 1.0000x reference)
#include <cuda_runtime.h>
#include <cuda_fp16.h>
#include <mma.h>
#include <cstdint>
#include <cfloat>

using namespace nvcuda;

#define B_   256
#define P_   128
#define K_   512
#define HID_ 64
#define EMB_ 1536   // K_ + 1024 (frame)

#define NPROD 528   // 512 qf blocks + 16 W1k-convert blocks
#define NATTN 256

// ---------------- device scratch ----------------
__device__ float g_qfp[16][B_][HID_];   // qf partials [d-slice][batch][h]
__device__ __half g_Bf[K_ * HID_];      // W1k as fp16, row-major [k][h]
__device__ int g_qf_done  = 0;          // producer completion counter
__device__ int g_attn_done = 0;         // consumer completion counter (for reset)

// ---------------- helpers ----------------
__device__ __forceinline__ uint32_t smem_u32(const void* p) {
    uint32_t a;
    asm("{ .reg .u64 t; cvta.to.shared.u64 t, %1; cvt.u32.u64 %0, t; }" : "=r"(a) : "l"(p));
    return a;
}
__device__ __forceinline__ void cp_async16(uint32_t dst, const void* src) {
    asm volatile("cp.async.cg.shared.global [%0], [%1], 16;" :: "r"(dst), "l"(src) : "memory");
}
#define CP_COMMIT()  asm volatile("cp.async.commit_group;" ::: "memory")
#define CP_WAIT(n)   asm volatile("cp.async.wait_group %0;" :: "n"(n) : "memory")

union PackH4 { __half h[4]; uint2 u; };

// ---------------- SMEM layout (shared by all roles) ----------------
// attn role:
//   [0)      sA : 2 bufs x 128 x 72 half = 36864  } sH (128x68 f32) aliases [0,34816)
//   [36864)  sB : 3 bufs x 64 x 72 half = 27648
//   [64512)  sQF 64f | [64768) sW2 64f | [65024) sScore 128f
//   [65536)  sCtx : 1024 f32 = 4096
// qf role: sX = [0, 4096)
#define OFF_A   0u
#define ABUF    18432u
#define OFF_B   36864u
#define BBUF    9216u
#define OFF_QF  64512u
#define OFF_W2  64768u
#define OFF_SC  65024u
#define OFF_CTX 65536u
#define SMEM_BYTES 69632
#define LDA 72
#define LDB 72
#define LDH 68

__global__ __launch_bounds__(256, 2)
void fused_all(const float* __restrict__ query,
               const float* __restrict__ keys,
               const float* __restrict__ frame,
               const int*   __restrict__ mask,
               const float* __restrict__ W1,
               const float* __restrict__ W2,
               float* __restrict__ out) {
    extern __shared__ char smem[];
    const int bid = blockIdx.x;
    const int t   = threadIdx.x;

    // ================= producer roles (blocks 0..527) =================
    if (bid < NPROD) {
        if (bid >= 512) {
            // W1k -> fp16 convert (16 blocks)
            const int base = (bid - 512) * 2048 + t * 8;
            PackH4 p[2];
            #pragma unroll
            for (int v = 0; v < 2; v++) {
                float4 x = *(const float4*)(W1 + base + v * 4);
                p[v].h[0] = __float2half_rn(x.x);
                p[v].h[1] = __float2half_rn(x.y);
                p[v].h[2] = __float2half_rn(x.z);
                p[v].h[3] = __float2half_rn(x.w);
            }
            *(uint4*)(g_Bf + base) = make_uint4(p[0].u.x, p[0].u.y, p[1].u.x, p[1].u.y);
        } else {
            // qf partials (512 blocks)
            float* sX = (float*)smem;   // 8 x 128 floats
            const int bg = bid & 31;
            const int ds = bid >> 5;
            const float* src = (ds < 8) ? (query + ds * 128) : (frame + (ds - 8) * 128);
            #pragma unroll
            for (int j = 0; j < 4; j++) {
                int lin = j * 256 + t;
                int bb = lin >> 7, ff = lin & 127;
                sX[bb * 128 + ff] = src[(size_t)(bg * 8 + bb) * 1024 + ff];
            }
            __syncthreads();
            const int h  = t & 63;
            const int bs = t >> 6;
            const float* w = W1 + (size_t)(K_ + ds * 128) * HID_ + h;
            float a0 = 0.f, a1 = 0.f;
            #pragma unroll 8
            for (int d = 0; d < 128; d++) {
                float wv = w[(size_t)d * HID_];
                a0 = fmaf(wv, sX[bs * 128 + d],       a0);
                a1 = fmaf(wv, sX[(bs + 4) * 128 + d], a1);
            }
            g_qfp[ds][bg * 8 + bs][h]     = a0;
            g_qfp[ds][bg * 8 + bs + 4][h] = a1;
        }
        // publish
        __threadfence();
        __syncthreads();
        if (t == 0) atomicAdd(&g_qf_done, 1);
        return;
    }

    // ================= consumer: attention (blocks 528..783) =================
    // gate: wait for all producers
    if (t == 0) {
        int v;
        do {
            asm volatile("ld.global.acquire.gpu.s32 %0, [%1];"
                         : "=r"(v) : "l"(&g_qf_done) : "memory");
            if (v < NPROD) __nanosleep(128);
        } while (v < NPROD);
    }
    __syncthreads();

    const uint32_t sb = smem_u32(smem);
    float* sQF    = (float*)(smem + OFF_QF);
    float* sW2    = (float*)(smem + OFF_W2);
    float* sScore = (float*)(smem + OFF_SC);
    float* sCtx   = (float*)(smem + OFF_CTX);
    float* sH     = (float*)(smem + OFF_A);   // alias after GEMM

    const int b = bid - NPROD;
    const int wid = t >> 5;
    const float* keyb = keys  + (size_t)b * P_ * K_;
    const float* fb   = frame + (size_t)b * 1024;

    const int arow = t >> 4;
    const int ac4  = t & 15;
    const int brow = t >> 3;
    const int bc8  = t & 7;

    // ---- prologue ----
    float4 ra[8];
    #pragma unroll
    for (int i = 0; i < 8; i++)
        ra[i] = *(const float4*)(keyb + (size_t)(arow + 16 * i) * K_ + ac4 * 4);
    #pragma unroll
    for (int i = 0; i < 2; i++) {
        int row = brow + 32 * i;
        cp_async16(sb + OFF_B + (uint32_t)(row * (LDB * 2) + bc8 * 16),
                   g_Bf + row * HID_ + bc8 * 8);
    }
    CP_COMMIT();
    #pragma unroll
    for (int i = 0; i < 2; i++) {
        int row = brow + 32 * i;
        cp_async16(sb + OFF_B + BBUF + (uint32_t)(row * (LDB * 2) + bc8 * 16),
                   g_Bf + 64 * HID_ + row * HID_ + bc8 * 8);
    }
    CP_COMMIT();

    if (t < HID_) {
        float s = 0.f;
        #pragma unroll
        for (int ds = 0; ds < 16; ds++) s += g_qfp[ds][b][t];
        sQF[t] = s;
        sW2[t] = W2[t];
    }

    {
        __half* sA0 = (__half*)(smem + OFF_A);
        #pragma unroll
        for (int i = 0; i < 8; i++) {
            PackH4 p;
            p.h[0] = __float2half_rn(ra[i].x);
            p.h[1] = __float2half_rn(ra[i].y);
            p.h[2] = __float2half_rn(ra[i].z);
            p.h[3] = __float2half_rn(ra[i].w);
            *(uint2*)(sA0 + (arow + 16 * i) * LDA + ac4 * 4) = p.u;
        }
    }
    #pragma unroll
    for (int i = 0; i < 8; i++)
        ra[i] = *(const float4*)(keyb + (size_t)(arow + 16 * i) * K_ + 64 + ac4 * 4);

    CP_WAIT(1);
    __syncthreads();

    // ---- GEMM mainloop: one barrier per chunk, B triple-buffered ----
    const int wm = wid & 3;
    const int wn = wid >> 2;
    wmma::fragment<wmma::accumulator, 16, 16, 16, float> acc[2][2];
    #pragma unroll
    for (int i = 0; i < 2; i++)
        #pragma unroll
        for (int j = 0; j < 2; j++) wmma::fill_fragment(acc[i][j], 0.f);

    #pragma unroll
    for (int kc = 0; kc < 8; kc++) {
        if (kc < 7) {
            __half* sAn = (__half*)(smem + OFF_A + ((kc + 1) & 1) * ABUF);
            #pragma unroll
            for (int i = 0; i < 8; i++) {
                PackH4 p;
                p.h[0] = __float2half_rn(ra[i].x);
                p.h[1] = __float2half_rn(ra[i].y);
                p.h[2] = __float2half_rn(ra[i].z);
                p.h[3] = __float2half_rn(ra[i].w);
                *(uint2*)(sAn + (arow + 16 * i) * LDA + ac4 * 4) = p.u;
            }
        }
        if (kc < 6) {
            #pragma unroll
            for (int i = 0; i < 8; i++)
                ra[i] = *(const float4*)(keyb + (size_t)(arow + 16 * i) * K_ + (kc + 2) * 64 + ac4 * 4);
        }
        if (kc < 6) {
            const uint32_t nb = OFF_B + (uint32_t)(((kc + 2) % 3)) * BBUF;
            #pragma unroll
            for (int i = 0; i < 2; i++) {
                int row = brow + 32 * i;
                cp_async16(sb + nb + (uint32_t)(row * (LDB * 2) + bc8 * 16),
                           g_Bf + (kc + 2) * 64 * HID_ + row * HID_ + bc8 * 8);
            }
            CP_COMMIT();
        }

        const __half* sA = (const __half*)(smem + OFF_A + (kc & 1) * ABUF);
        const __half* sB = (const __half*)(smem + OFF_B + (kc % 3) * BBUF);
        #pragma unroll
        for (int ks = 0; ks < 4; ks++) {
            wmma::fragment<wmma::matrix_a, 16, 16, 16, __half, wmma::row_major> a[2];
            #pragma unroll
            for (int i = 0; i < 2; i++)
                wmma::load_matrix_sync(a[i], sA + (wm * 32 + i * 16) * LDA + ks * 16, LDA);
            #pragma unroll
            for (int nf = 0; nf < 2; nf++) {
                wmma::fragment<wmma::matrix_b, 16, 16, 16, __half, wmma::row_major> bf;
                wmma::load_matrix_sync(bf, sB + (ks * 16) * LDB + wn * 32 + nf * 16, LDB);
                #pragma unroll
                for (int i = 0; i < 2; i++)
                    wmma::mma_sync(acc[i][nf], a[i], bf, acc[i][nf]);
            }
        }

        if (kc < 6) CP_WAIT(1);
        __syncthreads();
    }

    #pragma unroll
    for (int i = 0; i < 2; i++)
        #pragma unroll
        for (int j = 0; j < 2; j++)
            wmma::store_matrix_sync(sH + (wm * 32 + i * 16) * LDH + wn * 32 + j * 16,
                                    acc[i][j], LDH, wmma::mem_row_major);
    __syncthreads();

    // ---- scores ----
    if (t < P_) {
        float sc = 0.f;
        const float* hr = sH + t * LDH;
        #pragma unroll
        for (int j = 0; j < HID_; j++) {
            float hv = hr[j] + sQF[j];
            sc = fmaf(fmaxf(hv, 0.f), sW2[j], sc);
        }
        sScore[t] = sc;
    }
    __syncthreads();

    // ---- masked softmax ----
    if (t < 32) {
        int   mk[4];
        float scv[4], e[4];
        float mx = -FLT_MAX;
        #pragma unroll
        for (int i = 0; i < 4; i++) {
            int p = t + 32 * i;
            mk[i]  = mask[b * P_ + p];
            scv[i] = sScore[p];
            if (mk[i]) mx = fmaxf(mx, scv[i]);
        }
        #pragma unroll
        for (int off = 16; off >= 1; off >>= 1)
            mx = fmaxf(mx, __shfl_xor_sync(0xffffffffu, mx, off));
        float sum = 0.f;
        #pragma unroll
        for (int i = 0; i < 4; i++) { e[i] = mk[i] ? __expf(scv[i] - mx) : 0.f; sum += e[i]; }
        #pragma unroll
        for (int off = 16; off >= 1; off >>= 1)
            sum += __shfl_xor_sync(0xffffffffu, sum, off);
        float inv = 1.0f / sum;
        #pragma unroll
        for (int i = 0; i < 4; i++) {
            int p = t + 32 * i;
            float w = e[i] * inv;
            sScore[p] = w;
            out[(size_t)B_ * EMB_ + (size_t)b * P_ + p] = w;
        }
    }
    __syncthreads();

    // ---- context, vectorized split-p ----
    {
        const int th = t & 127;
        const int ph = (t >> 7) * 64;
        const float* kp = keyb + (size_t)ph * K_ + th * 4;
        float4 cacc = make_float4(0.f, 0.f, 0.f, 0.f);
        #pragma unroll 8
        for (int p = 0; p < 64; p++) {
            float w = sScore[ph + p];
            float4 kv = *(const float4*)(kp + (size_t)p * K_);
            cacc.x = fmaf(w, kv.x, cacc.x);
            cacc.y = fmaf(w, kv.y, cacc.y);
            cacc.z = fmaf(w, kv.z, cacc.z);
            cacc.w = fmaf(w, kv.w, cacc.w);
        }
        *(float4*)(sCtx + (t >> 7) * 512 + th * 4) = cacc;
    }
    __syncthreads();
    {
        float* eb = out + (size_t)b * EMB_;
        if (t < 128) {
            float4 a = *(const float4*)(sCtx + t * 4);
            float4 c = *(const float4*)(sCtx + 512 + t * 4);
            a.x += c.x; a.y += c.y; a.z += c.z; a.w += c.w;
            *(float4*)(eb + t * 4) = a;
        }
        #pragma unroll
        for (int i = 0; i < 4; i++)
            eb[K_ + t + 256 * i] = fb[t + 256 * i];
    }

    // ---- counter reset for next (graph-replayed) launch ----
    __syncthreads();
    if (t == 0) {
        int old = atomicAdd(&g_attn_done, 1);
        if (old == NATTN - 1) {
            g_qf_done  = 0;
            g_attn_done = 0;
            __threadfence();
        }
    }
}

extern "C" void kernel_launch(void* const* d_in, const int* in_sizes, int n_in,
                              void* d_out, int out_size) {
    const float* query = (const float*)d_in[0];
    const float* keys  = (const float*)d_in[1];
    const float* frame = (const float*)d_in[2];
    const int*   mask  = (const int*)d_in[3];
    const float* W1    = (const float*)d_in[4];
    const float* W2    = (const float*)d_in[5];
    float* out = (float*)d_out;

    static int cfg_done = 0;
    if (!cfg_done) {
        cudaFuncSetAttribute(fused_all, cudaFuncAttributeMaxDynamicSharedMemorySize, SMEM_BYTES);
        cfg_done = 1;
    }

    fused_all<<<NPROD + NATTN, 256, SMEM_BYTES>>>(query, keys, frame, mask, W1, W2, out);
}

// round 12
// speedup vs baseline: 1.2827x; 1.2827x over previous
#include <cuda_runtime.h>
#include <cuda_fp16.h>
#include <mma.h>
#include <cstdint>
#include <cfloat>

using namespace nvcuda;

#define B_   256
#define P_   128
#define K_   512
#define HID_ 64
#define EMB_ 1536   // K_ + 1024 (frame)

#define NCONV 16
#define NQF   128
#define NPROD (NCONV + NQF)   // 144
#define NATTN 256

// ---------------- device scratch ----------------
__device__ float g_qfp[16][B_][HID_];   // qf partials [d-slice][batch][h]
__device__ __half g_Bf[K_ * HID_];      // W1k as fp16, row-major [k][h]
__device__ int g_conv_done = 0;
__device__ int g_qf_done   = 0;
__device__ int g_attn_done = 0;

// ---------------- helpers ----------------
__device__ __forceinline__ uint32_t smem_u32(const void* p) {
    uint32_t a;
    asm("{ .reg .u64 t; cvta.to.shared.u64 t, %1; cvt.u32.u64 %0, t; }" : "=r"(a) : "l"(p));
    return a;
}
__device__ __forceinline__ void cp_async16(uint32_t dst, const void* src) {
    asm volatile("cp.async.cg.shared.global [%0], [%1], 16;" :: "r"(dst), "l"(src) : "memory");
}
#define CP_COMMIT()  asm volatile("cp.async.commit_group;" ::: "memory")
#define CP_WAIT(n)   asm volatile("cp.async.wait_group %0;" :: "n"(n) : "memory")

__device__ __forceinline__ void spin_until(const int* ctr, int target) {
    int v;
    do {
        asm volatile("ld.global.acquire.gpu.s32 %0, [%1];" : "=r"(v) : "l"(ctr) : "memory");
        if (v < target) __nanosleep(64);
    } while (v < target);
}

union PackH4 { __half h[4]; uint2 u; };

// ---------------- SMEM layout ----------------
// attn role:
//   [0)      sA : 2 x 128 x 72 half = 36864  } sH (128x68 f32) aliases [0,34816)
//   [36864)  sB : 3 x 64 x 72 half = 27648
//   [64512)  sQF 64f | [64768) sW2 64f | [65024) sScore 128f
//   [65536)  sCtx : 1024 f32 = 4096
// qf role: sX = 32 x 128 f32 = 16384 at [0)
#define OFF_A   0u
#define ABUF    18432u
#define OFF_B   36864u
#define BBUF    9216u
#define OFF_QF  64512u
#define OFF_W2  64768u
#define OFF_SC  65024u
#define OFF_CTX 65536u
#define SMEM_BYTES 69632
#define LDA 72
#define LDB 72
#define LDH 68

__global__ __launch_bounds__(256, 2)
void fused_all(const float* __restrict__ query,
               const float* __restrict__ keys,
               const float* __restrict__ frame,
               const int*   __restrict__ mask,
               const float* __restrict__ W1,
               const float* __restrict__ W2,
               float* __restrict__ out) {
    extern __shared__ char smem[];
    const int bid = blockIdx.x;
    const int t   = threadIdx.x;

    // ============ role 1: W1k -> fp16 converters (blocks 0..15) ============
    if (bid < NCONV) {
        const int base = bid * 2048 + t * 8;
        PackH4 p[2];
        #pragma unroll
        for (int v = 0; v < 2; v++) {
            float4 x = *(const float4*)(W1 + base + v * 4);
            p[v].h[0] = __float2half_rn(x.x);
            p[v].h[1] = __float2half_rn(x.y);
            p[v].h[2] = __float2half_rn(x.z);
            p[v].h[3] = __float2half_rn(x.w);
        }
        *(uint4*)(g_Bf + base) = make_uint4(p[0].u.x, p[0].u.y, p[1].u.x, p[1].u.y);
        __threadfence();
        __syncthreads();
        if (t == 0) atomicAdd(&g_conv_done, 1);
        return;
    }

    // ============ role 2: qf tile-GEMMs (blocks 16..143) ============
    if (bid < NPROD) {
        float* sX = (float*)smem;                  // [32][128]
        const int ds = (bid - NCONV) >> 3;         // 0..15
        const int bg = (bid - NCONV) & 7;          // 0..7 (32 batches each)
        const float* src = (ds < 8) ? (query + ds * 128) : (frame + (ds - 8) * 128);

        // stage x: 32 batches x 128 floats
        #pragma unroll
        for (int j = 0; j < 4; j++) {
            int idx = j * 256 + t;                 // float4 index
            int row = idx >> 5, c4 = idx & 31;
            *(float4*)(sX + row * 128 + c4 * 4) =
                *(const float4*)(src + (size_t)(bg * 32 + row) * 1024 + c4 * 4);
        }
        __syncthreads();

        const int h  = t & 63;                     // output h
        const int bq = t >> 6;                     // 0..3 -> batches bq*8..bq*8+7
        const float* w = W1 + (size_t)(K_ + ds * 128) * HID_ + h;
        float acc[8] = {0.f,0.f,0.f,0.f,0.f,0.f,0.f,0.f};
        #pragma unroll 4
        for (int d = 0; d < 128; d++) {
            float wv = w[(size_t)d * HID_];
            #pragma unroll
            for (int i = 0; i < 8; i++)
                acc[i] = fmaf(wv, sX[(bq * 8 + i) * 128 + d], acc[i]);
        }
        #pragma unroll
        for (int i = 0; i < 8; i++)
            g_qfp[ds][bg * 32 + bq * 8 + i][h] = acc[i];
        __threadfence();
        __syncthreads();
        if (t == 0) atomicAdd(&g_qf_done, 1);
        return;
    }

    // ============ role 3: attention (blocks 144..399) ============
    const uint32_t sb = smem_u32(smem);
    float* sQF    = (float*)(smem + OFF_QF);
    float* sW2    = (float*)(smem + OFF_W2);
    float* sScore = (float*)(smem + OFF_SC);
    float* sCtx   = (float*)(smem + OFF_CTX);
    float* sH     = (float*)(smem + OFF_A);   // alias after GEMM

    const int b = bid - NPROD;
    const int wid = t >> 5;
    const float* keyb = keys  + (size_t)b * P_ * K_;
    const float* fb   = frame + (size_t)b * 1024;

    const int arow = t >> 4;
    const int ac4  = t & 15;
    const int brow = t >> 3;
    const int bc8  = t & 7;

    // ---- prologue: A chunk 0 LDG first (covers the conv gate) ----
    float4 ra[8];
    #pragma unroll
    for (int i = 0; i < 8; i++)
        ra[i] = *(const float4*)(keyb + (size_t)(arow + 16 * i) * K_ + ac4 * 4);

    if (t < HID_) sW2[t] = W2[t];

    // gate: g_Bf ready (converters are blocks 0..15, wave-1 resident)
    if (t == 0) spin_until(&g_conv_done, NCONV);
    __syncthreads();

    #pragma unroll
    for (int i = 0; i < 2; i++) {
        int row = brow + 32 * i;
        cp_async16(sb + OFF_B + (uint32_t)(row * (LDB * 2) + bc8 * 16),
                   g_Bf + row * HID_ + bc8 * 8);
    }
    CP_COMMIT();
    #pragma unroll
    for (int i = 0; i < 2; i++) {
        int row = brow + 32 * i;
        cp_async16(sb + OFF_B + BBUF + (uint32_t)(row * (LDB * 2) + bc8 * 16),
                   g_Bf + 64 * HID_ + row * HID_ + bc8 * 8);
    }
    CP_COMMIT();

    {
        __half* sA0 = (__half*)(smem + OFF_A);
        #pragma unroll
        for (int i = 0; i < 8; i++) {
            PackH4 p;
            p.h[0] = __float2half_rn(ra[i].x);
            p.h[1] = __float2half_rn(ra[i].y);
            p.h[2] = __float2half_rn(ra[i].z);
            p.h[3] = __float2half_rn(ra[i].w);
            *(uint2*)(sA0 + (arow + 16 * i) * LDA + ac4 * 4) = p.u;
        }
    }
    #pragma unroll
    for (int i = 0; i < 8; i++)
        ra[i] = *(const float4*)(keyb + (size_t)(arow + 16 * i) * K_ + 64 + ac4 * 4);

    CP_WAIT(1);
    __syncthreads();

    // ---- GEMM mainloop (R10 structure: 1 barrier/chunk, B triple-buffered) ----
    const int wm = wid & 3;
    const int wn = wid >> 2;
    wmma::fragment<wmma::accumulator, 16, 16, 16, float> acc[2][2];
    #pragma unroll
    for (int i = 0; i < 2; i++)
        #pragma unroll
        for (int j = 0; j < 2; j++) wmma::fill_fragment(acc[i][j], 0.f);

    #pragma unroll
    for (int kc = 0; kc < 8; kc++) {
        if (kc < 7) {
            __half* sAn = (__half*)(smem + OFF_A + ((kc + 1) & 1) * ABUF);
            #pragma unroll
            for (int i = 0; i < 8; i++) {
                PackH4 p;
                p.h[0] = __float2half_rn(ra[i].x);
                p.h[1] = __float2half_rn(ra[i].y);
                p.h[2] = __float2half_rn(ra[i].z);
                p.h[3] = __float2half_rn(ra[i].w);
                *(uint2*)(sAn + (arow + 16 * i) * LDA + ac4 * 4) = p.u;
            }
        }
        if (kc < 6) {
            #pragma unroll
            for (int i = 0; i < 8; i++)
                ra[i] = *(const float4*)(keyb + (size_t)(arow + 16 * i) * K_ + (kc + 2) * 64 + ac4 * 4);
        }
        if (kc < 6) {
            const uint32_t nb = OFF_B + (uint32_t)(((kc + 2) % 3)) * BBUF;
            #pragma unroll
            for (int i = 0; i < 2; i++) {
                int row = brow + 32 * i;
                cp_async16(sb + nb + (uint32_t)(row * (LDB * 2) + bc8 * 16),
                           g_Bf + (kc + 2) * 64 * HID_ + row * HID_ + bc8 * 8);
            }
            CP_COMMIT();
        }

        const __half* sA = (const __half*)(smem + OFF_A + (kc & 1) * ABUF);
        const __half* sB = (const __half*)(smem + OFF_B + (kc % 3) * BBUF);
        #pragma unroll
        for (int ks = 0; ks < 4; ks++) {
            wmma::fragment<wmma::matrix_a, 16, 16, 16, __half, wmma::row_major> a[2];
            #pragma unroll
            for (int i = 0; i < 2; i++)
                wmma::load_matrix_sync(a[i], sA + (wm * 32 + i * 16) * LDA + ks * 16, LDA);
            #pragma unroll
            for (int nf = 0; nf < 2; nf++) {
                wmma::fragment<wmma::matrix_b, 16, 16, 16, __half, wmma::row_major> bf;
                wmma::load_matrix_sync(bf, sB + (ks * 16) * LDB + wn * 32 + nf * 16, LDB);
                #pragma unroll
                for (int i = 0; i < 2; i++)
                    wmma::mma_sync(acc[i][nf], a[i], bf, acc[i][nf]);
            }
        }

        if (kc < 6) CP_WAIT(1);
        __syncthreads();
    }

    #pragma unroll
    for (int i = 0; i < 2; i++)
        #pragma unroll
        for (int j = 0; j < 2; j++)
            wmma::store_matrix_sync(sH + (wm * 32 + i * 16) * LDH + wn * 32 + j * 16,
                                    acc[i][j], LDH, wmma::mem_row_major);

    // gate: qf partials ready (producers dispatched long before; ~0 wait)
    if (t == 0) spin_until(&g_qf_done, NQF);
    __syncthreads();

    if (t < HID_) {
        float s = 0.f;
        #pragma unroll
        for (int ds = 0; ds < 16; ds++) s += g_qfp[ds][b][t];
        sQF[t] = s;
    }
    __syncthreads();

    // ---- scores: relu(H + qf) . W2 ----
    if (t < P_) {
        float sc = 0.f;
        const float* hr = sH + t * LDH;
        #pragma unroll
        for (int j = 0; j < HID_; j++) {
            float hv = hr[j] + sQF[j];
            sc = fmaf(fmaxf(hv, 0.f), sW2[j], sc);
        }
        sScore[t] = sc;
    }
    __syncthreads();

    // ---- masked softmax ----
    if (t < 32) {
        int   mk[4];
        float scv[4], e[4];
        float mx = -FLT_MAX;
        #pragma unroll
        for (int i = 0; i < 4; i++) {
            int p = t + 32 * i;
            mk[i]  = mask[b * P_ + p];
            scv[i] = sScore[p];
            if (mk[i]) mx = fmaxf(mx, scv[i]);
        }
        #pragma unroll
        for (int off = 16; off >= 1; off >>= 1)
            mx = fmaxf(mx, __shfl_xor_sync(0xffffffffu, mx, off));
        float sum = 0.f;
        #pragma unroll
        for (int i = 0; i < 4; i++) { e[i] = mk[i] ? __expf(scv[i] - mx) : 0.f; sum += e[i]; }
        #pragma unroll
        for (int off = 16; off >= 1; off >>= 1)
            sum += __shfl_xor_sync(0xffffffffu, sum, off);
        float inv = 1.0f / sum;
        #pragma unroll
        for (int i = 0; i < 4; i++) {
            int p = t + 32 * i;
            float w = e[i] * inv;
            sScore[p] = w;
            out[(size_t)B_ * EMB_ + (size_t)b * P_ + p] = w;
        }
    }
    __syncthreads();

    // ---- context, vectorized split-p ----
    {
        const int th = t & 127;
        const int ph = (t >> 7) * 64;
        const float* kp = keyb + (size_t)ph * K_ + th * 4;
        float4 cacc = make_float4(0.f, 0.f, 0.f, 0.f);
        #pragma unroll 8
        for (int p = 0; p < 64; p++) {
            float w = sScore[ph + p];
            float4 kv = *(const float4*)(kp + (size_t)p * K_);
            cacc.x = fmaf(w, kv.x, cacc.x);
            cacc.y = fmaf(w, kv.y, cacc.y);
            cacc.z = fmaf(w, kv.z, cacc.z);
            cacc.w = fmaf(w, kv.w, cacc.w);
        }
        *(float4*)(sCtx + (t >> 7) * 512 + th * 4) = cacc;
    }
    __syncthreads();
    {
        float* eb = out + (size_t)b * EMB_;
        if (t < 128) {
            float4 a = *(const float4*)(sCtx + t * 4);
            float4 c = *(const float4*)(sCtx + 512 + t * 4);
            a.x += c.x; a.y += c.y; a.z += c.z; a.w += c.w;
            *(float4*)(eb + t * 4) = a;
        }
        #pragma unroll
        for (int i = 0; i < 4; i++)
            eb[K_ + t + 256 * i] = fb[t + 256 * i];
    }

    // ---- counter reset for graph replay determinism ----
    __syncthreads();
    if (t == 0) {
        int old = atomicAdd(&g_attn_done, 1);
        if (old == NATTN - 1) {
            g_conv_done = 0;
            g_qf_done   = 0;
            g_attn_done = 0;
            __threadfence();
        }
    }
}

extern "C" void kernel_launch(void* const* d_in, const int* in_sizes, int n_in,
                              void* d_out, int out_size) {
    const float* query = (const float*)d_in[0];
    const float* keys  = (const float*)d_in[1];
    const float* frame = (const float*)d_in[2];
    const int*   mask  = (const int*)d_in[3];
    const float* W1    = (const float*)d_in[4];
    const float* W2    = (const float*)d_in[5];
    float* out = (float*)d_out;

    static int cfg_done = 0;
    if (!cfg_done) {
        cudaFuncSetAttribute(fused_all, cudaFuncAttributeMaxDynamicSharedMemorySize, SMEM_BYTES);
        cfg_done = 1;
    }

    fused_all<<<NPROD + NATTN, 256, SMEM_BYTES>>>(query, keys, frame, mask, W1, W2, out);
}